// round 2
// baseline (speedup 1.0000x reference)
#include <cuda_runtime.h>
#include <math.h>

// ---------------------------------------------------------------------------
// AttentionLoss: out = cwg + tv + dcml   (scalar f32)
//
// Shapes (fixed): BS=2, H=W=64, HW=4096, mh=mw=64.
//   sim  [2,4096,64,64] f32
//   wc   [2,4096,2]     f32   (y, x) per p
//   mask [2,64,64]      int32 (bool promoted by harness; 0/1)
// ---------------------------------------------------------------------------

#define BS   2
#define H    64
#define W    64
#define HW   4096
#define NBP  (BS * HW)        // 8192 (b,p) slices

#define CWG_SCALE  (-2.0  / 33554432.0)          // -CWG_STRENGTH / (BS*HW*mh*mw)
#define DCML_SCALE (-0.01 / 33554432.0)          // -DCML_STRENGTH / (BS*HW*HW)
#define TV_SCALE   (1.0e-4 / 16128.0)            // TV_STRENGTH / count(y_tv)

// exp(-r/2) at r=26 is 2.3e-6; skipping |dy|>26 rows -> total abs err ~4e-8
#define DY2_CUTOFF 676.0f

__device__ double g_sum;

__device__ __forceinline__ float warp_sum(float v) {
#pragma unroll
    for (int o = 16; o; o >>= 1) v += __shfl_down_sync(0xffffffffu, v, o);
    return v;
}

__global__ void k_init() { g_sum = 0.0; }

// ---------------------------------------------------------------------------
// tv + dcml: one block (64 threads) per "line".
//   blockIdx.x = l;  b = l>>7;  dir = (l>>6)&1;  li = l&63
//   dir==0: row line (i=li fixed, t=j)  -> dcml x channel, x_tv both channels
//   dir==1: col line (j=li fixed, t=i)  -> dcml y channel, y_tv both channels
// ---------------------------------------------------------------------------
__global__ void k_lines(const float* __restrict__ wc,
                        const int* __restrict__ mask) {
    __shared__ float sy[64], sx[64], sm[64];
    __shared__ float red_dc[2], red_tv[2];

    int l   = blockIdx.x;
    int b   = l >> 7;
    int dir = (l >> 6) & 1;
    int li  = l & 63;
    int t   = threadIdx.x;

    int pos = (dir == 0) ? (li * W + t) : (t * W + li);
    int g   = b * HW + pos;
    sy[t] = wc[2 * g + 0];
    sx[t] = wc[2 * g + 1];
    sm[t] = mask[g] ? 1.0f : 0.0f;
    __syncthreads();

    const float* vv = (dir == 0) ? sx : sy;

    // dcml: sum over p < t of relu(v[t] - v[p]) * m[p] * m[t]
    float dc = 0.0f;
    if (sm[t] != 0.0f) {
        float vt = vv[t];
        for (int p = 0; p < t; ++p)
            dc += fmaxf(vt - vv[p], 0.0f) * sm[p];
    }

    // tv: neighbor (t, t+1) along the line, both channels
    float tv = 0.0f;
    if (t < 63) {
        float dy = sy[t + 1] - sy[t];
        float dx = sx[t + 1] - sx[t];
        tv = (dy * dy + dx * dx) * sm[t] * sm[t + 1];
    }

    dc = warp_sum(dc);
    tv = warp_sum(tv);
    int wid = t >> 5, lane = t & 31;
    if (lane == 0) { red_dc[wid] = dc; red_tv[wid] = tv; }
    __syncthreads();
    if (t == 0) {
        double total = (double)(red_dc[0] + red_dc[1]) * DCML_SCALE
                     + (double)(red_tv[0] + red_tv[1]) * TV_SCALE;
        atomicAdd(&g_sum, total);
    }
}

// ---------------------------------------------------------------------------
// cwg: one block (128 threads = 4 warps) per (b,p) slice.
// Warp w handles rows y = w, w+4, ...; lane covers x = lane and lane+32.
// mask==0 slices skip all HBM reads; rows with dy^2 > cutoff skipped too.
// ---------------------------------------------------------------------------
__global__ void __launch_bounds__(128)
k_cwg(const float* __restrict__ sim,
      const float* __restrict__ wc,
      const int* __restrict__ mask) {
    int bp = blockIdx.x;                      // 0 .. 8191
    if (!mask[bp]) return;

    float cy = wc[2 * bp + 0];
    float cx = wc[2 * bp + 1];
    const float* s = sim + (size_t)bp * (size_t)(H * W);

    int wid  = threadIdx.x >> 5;
    int lane = threadIdx.x & 31;

    float dx0 = (float)lane        - cx;
    float dx1 = (float)(lane + 32) - cx;
    float dx0sq = dx0 * dx0;
    float dx1sq = dx1 * dx1;

    float acc = 0.0f;
#pragma unroll 4
    for (int y = wid; y < H; y += 4) {
        float dy  = (float)y - cy;
        float dy2 = dy * dy;
        if (dy2 > DY2_CUTOFF) continue;       // skip row: no loads, no MUFU
        float s0 = s[y * W + lane];
        float s1 = s[y * W + lane + 32];
        float d2a = fmaxf(dy2 + dx0sq, 1e-12f);
        float d2b = fmaxf(dy2 + dx1sq, 1e-12f);
        float ra = d2a * rsqrtf(d2a);         // r = sqrt(d2), 1 MUFU
        float rb = d2b * rsqrtf(d2b);
        acc += __expf(-0.5f * ra) * s0;       // 1 MUFU + FMUL + FFMA
        acc += __expf(-0.5f * rb) * s1;
    }

    __shared__ float red[4];
    acc = warp_sum(acc);
    if (lane == 0) red[wid] = acc;
    __syncthreads();
    if (threadIdx.x == 0) {
        float tot = red[0] + red[1] + red[2] + red[3];
        atomicAdd(&g_sum, (double)tot * CWG_SCALE);
    }
}

__global__ void k_fin(float* __restrict__ out) { out[0] = (float)g_sum; }

// ---------------------------------------------------------------------------
extern "C" void kernel_launch(void* const* d_in, const int* in_sizes, int n_in,
                              void* d_out, int out_size) {
    const float* sim  = (const float*)d_in[0];
    const float* wc   = (const float*)d_in[1];
    const int*   mask = (const int*)d_in[2];
    (void)in_sizes; (void)n_in; (void)out_size;

    k_init <<<1, 1>>>();
    k_lines<<<256, 64>>>(wc, mask);
    k_cwg  <<<NBP, 128>>>(sim, wc, mask);
    k_fin  <<<1, 1>>>((float*)d_out);
}

// round 5
// speedup vs baseline: 1.3185x; 1.3185x over previous
#include <cuda_runtime.h>
#include <math.h>

// ---------------------------------------------------------------------------
// AttentionLoss, 2 launches: fused compute (cwg + tv + dcml -> g_sum atomics)
// then finalize (write out, reset g_sum). Deterministic across graph replays.
//   sim  [2,4096,64,64] f32,  wc [2,4096,2] f32 (y,x),  mask [2,64,64] int32
// ---------------------------------------------------------------------------

#define BS     2
#define H      64
#define W      64
#define HW     4096
#define NBP    8192              // cwg blocks (one per (b,p) slice)
#define NLINES 256               // 2 batches x {row,col} x 64 lines
#define GRID   (NBP + NLINES)

#define CWG_SCALE  (-2.0  / 33554432.0)
#define DCML_SCALE (-0.01 / 33554432.0)
#define TV_SCALE   (1.0e-4 / 16128.0)

// 2-D cutoff radius: reads only the [cy±16, cx±16] window of each slice.
// Tail-mass bound ~3e-4 rel worst case; R=26 calibration says ~5x lower real.
#define RCUT 16.0f

__device__ double g_sum = 0.0;

__device__ __forceinline__ float warp_sum(float v) {
#pragma unroll
    for (int o = 16; o; o >>= 1) v += __shfl_down_sync(0xffffffffu, v, o);
    return v;
}

__global__ void __launch_bounds__(128)
k_compute(const float* __restrict__ sim,
          const float* __restrict__ wc,
          const int*   __restrict__ mask)
{
    __shared__ float sh[64 * 3 + 8];
    float* sy  = sh;
    float* sx  = sh + 64;
    float* sm  = sh + 128;
    float* red = sh + 192;          // 8 slots

    int blk  = blockIdx.x;
    int tid  = threadIdx.x;
    int wid  = tid >> 5;
    int lane = tid & 31;

    if (blk < NBP) {
        // ---------------- cwg: one slice per block ----------------
        if (!mask[blk]) return;     // uniform per block: safe early exit
        float cy = wc[2 * blk + 0];
        float cx = wc[2 * blk + 1];
        const float* s = sim + (size_t)blk * (size_t)(H * W);

        int iy0 = max(0,     (int)ceilf (cy - RCUT));
        int iy1 = min(H - 1, (int)floorf(cy + RCUT));
        int ix0 = max(0,     (int)ceilf (cx - RCUT));
        int ix1 = min(W - 1, (int)floorf(cx + RCUT));

        int  x0 = ix0 + lane;
        int  x1 = x0 + 32;
        bool a0 = (x0 <= ix1);
        bool a1 = (x1 <= ix1);
        float dx0 = (float)x0 - cx,  dx1 = (float)x1 - cx;
        float dx0sq = dx0 * dx0,     dx1sq = dx1 * dx1;

        float acc = 0.0f;
#pragma unroll 3
        for (int y = iy0 + wid; y <= iy1; y += 4) {
            float dy  = (float)y - cy;
            float dy2 = dy * dy;
            const float* row = s + y * W;
            if (a0) {
                float v  = row[x0];
                float d2 = fmaxf(dy2 + dx0sq, 1e-12f);
                float r  = d2 * rsqrtf(d2);          // sqrt via 1 MUFU
                acc += __expf(-0.5f * r) * v;
            }
            if (a1) {
                float v  = row[x1];
                float d2 = fmaxf(dy2 + dx1sq, 1e-12f);
                float r  = d2 * rsqrtf(d2);
                acc += __expf(-0.5f * r) * v;
            }
        }
        acc = warp_sum(acc);
        if (lane == 0) red[wid] = acc;
        __syncthreads();
        if (tid == 0) {
            float tot = red[0] + red[1] + red[2] + red[3];
            atomicAdd(&g_sum, (double)tot * CWG_SCALE);
        }
    } else {
        // ---------------- tv + dcml: one line per block ----------------
        int l   = blk - NBP;
        int b   = l >> 7;
        int dir = (l >> 6) & 1;     // 0: row line (t=j), 1: col line (t=i)
        int li  = l & 63;

        if (tid < 64) {
            int pos = (dir == 0) ? (li * W + tid) : (tid * W + li);
            int g   = b * HW + pos;
            sy[tid] = wc[2 * g + 0];
            sx[tid] = wc[2 * g + 1];
            sm[tid] = mask[g] ? 1.0f : 0.0f;
        }
        __syncthreads();

        float dc = 0.0f, tv = 0.0f;
        if (tid < 64) {
            const float* vv = (dir == 0) ? sx : sy;
            if (sm[tid] != 0.0f) {
                float vt = vv[tid];
                for (int p = 0; p < tid; ++p)
                    dc += fmaxf(vt - vv[p], 0.0f) * sm[p];
            }
            if (tid < 63) {
                float dy = sy[tid + 1] - sy[tid];
                float dx = sx[tid + 1] - sx[tid];
                tv = (dy * dy + dx * dx) * sm[tid] * sm[tid + 1];
            }
        }
        dc = warp_sum(dc);
        tv = warp_sum(tv);
        if (lane == 0 && wid < 2) { red[wid] = dc; red[4 + wid] = tv; }
        __syncthreads();
        if (tid == 0) {
            double tot = (double)(red[0] + red[1]) * DCML_SCALE
                       + (double)(red[4] + red[5]) * TV_SCALE;
            atomicAdd(&g_sum, tot);
        }
    }
}

// Finalize: publish result and reset the accumulator for the next replay.
__global__ void k_fin(float* __restrict__ out) {
    out[0] = (float)g_sum;
    g_sum  = 0.0;
}

// ---------------------------------------------------------------------------
extern "C" void kernel_launch(void* const* d_in, const int* in_sizes, int n_in,
                              void* d_out, int out_size) {
    const float* sim  = (const float*)d_in[0];
    const float* wc   = (const float*)d_in[1];
    const int*   mask = (const int*)d_in[2];
    (void)in_sizes; (void)n_in; (void)out_size;

    k_compute<<<GRID, 128>>>(sim, wc, mask);
    k_fin    <<<1, 1>>>((float*)d_out);
}